// round 3
// baseline (speedup 1.0000x reference)
#include <cuda_runtime.h>
#include <math.h>

#define Bn 16
#define Cn 256
#define Ln 64
#define Nn 8192
#define Hn 8
#define HC 32          // C / H
#define Mn 12
#define SQRT32 5.656854249492381f
#define RS_BN 0.9999950000374997f   // 1/sqrt(1 + 1e-5)
#define PI_F 3.14159265358979323846f

// ---------------- scratch (device globals; no allocation) ----------------
__device__ float g_qkv[Bn * 3 * Cn * Ln];   // (B,3,C,L)
__device__ float g_am [Bn * Cn * Ln];       // merged attention (B,C,L)
__device__ float g_enc[Bn * Cn * Ln];       // encoder output (B,C,L)
__device__ float g_xncol[Bn * Cn];          // xn_pre per (b,c) (const along n)
__device__ float g_y2[Bn * 3];              // head output per (b,k)

// ---------------- kernel 1: qkv = enc_w @ xt + enc_b ----------------
// grid (12, 16): 64-row tile x batch. block 256. micro-tile 4x4.
#define FMA4(acc, s, v) { acc.x = fmaf((s),(v).x,acc.x); acc.y = fmaf((s),(v).y,acc.y); \
                          acc.z = fmaf((s),(v).z,acc.z); acc.w = fmaf((s),(v).w,acc.w); }

__global__ void __launch_bounds__(256) k_qkv(const float* __restrict__ xt,
                                             const float* __restrict__ enc_w,
                                             const float* __restrict__ enc_b)
{
    __shared__ float4 xs4[128 * 16];   // 128 j-rows x 64 cols (as 16 float4) = 32KB
    const int b  = blockIdx.y;
    const int rt = blockIdx.x;               // row tile (64 rows)
    const float4* xb4 = (const float4*)(xt + b * Cn * Ln);

    const int rg = threadIdx.x >> 4;         // 0..15 -> rows rg*4..rg*4+3
    const int cg = threadIdx.x & 15;         // 0..15 -> cols cg*4..cg*4+3
    const int row0 = rt * 64 + rg * 4;

    const float4* w0p = (const float4*)(enc_w + (row0 + 0) * Cn);
    const float4* w1p = (const float4*)(enc_w + (row0 + 1) * Cn);
    const float4* w2p = (const float4*)(enc_w + (row0 + 2) * Cn);
    const float4* w3p = (const float4*)(enc_w + (row0 + 3) * Cn);

    float4 acc0 = {0,0,0,0}, acc1 = {0,0,0,0}, acc2 = {0,0,0,0}, acc3 = {0,0,0,0};

    for (int jc = 0; jc < 2; jc++) {
        // stage 128 x 64 chunk of X
        for (int i = threadIdx.x; i < 2048; i += 256) xs4[i] = xb4[jc * 2048 + i];
        __syncthreads();
        #pragma unroll 8
        for (int j4 = 0; j4 < 32; j4++) {
            const int jg = jc * 32 + j4;
            float4 w0 = w0p[jg], w1 = w1p[jg], w2 = w2p[jg], w3 = w3p[jg];
            float4 xa = xs4[(j4 * 4 + 0) * 16 + cg];
            float4 xb = xs4[(j4 * 4 + 1) * 16 + cg];
            float4 xc = xs4[(j4 * 4 + 2) * 16 + cg];
            float4 xd = xs4[(j4 * 4 + 3) * 16 + cg];
            FMA4(acc0, w0.x, xa); FMA4(acc0, w0.y, xb); FMA4(acc0, w0.z, xc); FMA4(acc0, w0.w, xd);
            FMA4(acc1, w1.x, xa); FMA4(acc1, w1.y, xb); FMA4(acc1, w1.z, xc); FMA4(acc1, w1.w, xd);
            FMA4(acc2, w2.x, xa); FMA4(acc2, w2.y, xb); FMA4(acc2, w2.z, xc); FMA4(acc2, w2.w, xd);
            FMA4(acc3, w3.x, xa); FMA4(acc3, w3.y, xb); FMA4(acc3, w3.z, xc); FMA4(acc3, w3.w, xd);
        }
        __syncthreads();
    }

    float4 accs[4] = {acc0, acc1, acc2, acc3};
    #pragma unroll
    for (int r = 0; r < 4; r++) {
        const int o = row0 + r;
        const float bias = enc_b[o];
        float4 res = accs[r];
        res.x += bias; res.y += bias; res.z += bias; res.w += bias;
        ((float4*)(g_qkv + (size_t)b * 3 * Cn * Ln + o * Ln))[cg] = res;
    }
}

// ---------------- kernel 2: encoder attention per (b,h) ----------------
// grid (H, B), block 64 (one thread per query position l)
__global__ void __launch_bounds__(64) k_attn()
{
    __shared__ float ks[64 * 33];
    __shared__ float vs[64 * 33];
    __shared__ float sc[64 * 65];
    const int h = blockIdx.x, b = blockIdx.y;
    const float* qb = g_qkv + (size_t)b * 3 * Cn * Ln + (h * HC) * Ln;
    const float* kb = qb + Cn * Ln;
    const float* vb = qb + 2 * Cn * Ln;
    const int t = threadIdx.x;

    for (int i = t; i < 2048; i += 64) {
        int cc = i >> 6, s = i & 63;
        ks[s * 33 + cc] = kb[cc * Ln + s];
        vs[s * 33 + cc] = vb[cc * Ln + s];
    }
    __syncthreads();

    const int l = t;
    float q[HC];
    #pragma unroll
    for (int cc = 0; cc < HC; cc++) q[cc] = qb[cc * Ln + l];

    float mx = -1e30f;
    for (int s = 0; s < 64; s++) {
        float d = 0.f;
        #pragma unroll
        for (int cc = 0; cc < HC; cc++) d = fmaf(q[cc], ks[s * 33 + cc], d);
        d *= SQRT32;
        sc[l * 65 + s] = d;
        mx = fmaxf(mx, d);
    }
    float sum = 0.f;
    for (int s = 0; s < 64; s++) {
        float e = __expf(sc[l * 65 + s] - mx);
        sc[l * 65 + s] = e;
        sum += e;
    }
    const float inv = 1.f / sum;
    float acc[HC];
    #pragma unroll
    for (int cc = 0; cc < HC; cc++) acc[cc] = 0.f;
    for (int s = 0; s < 64; s++) {
        float p = sc[l * 65 + s];
        #pragma unroll
        for (int cc = 0; cc < HC; cc++) acc[cc] = fmaf(p, vs[s * 33 + cc], acc[cc]);
    }
    float* out = g_am + (size_t)b * Cn * Ln + (h * HC) * Ln + l;
    #pragma unroll
    for (int cc = 0; cc < HC; cc++) out[cc * Ln] = acc[cc] * inv;
}

// ---------------- kernel 3: Fourier basis + residual ----------------
__global__ void __launch_bounds__(256) k_fourier(const float* __restrict__ xt,
                                                 const float* __restrict__ weights)
{
    const int idx = blockIdx.x * 256 + threadIdx.x;   // b*C*L + c*L + l
    const int c = (idx >> 6) & (Cn - 1);
    const float a = g_am[idx];
    const float phi = a * (PI_F / (float)Mn);
    float s1, c1;
    __sincosf(phi, &s1, &c1);
    const float* w = weights + c * (2 * Mn);
    float acc = w[Mn];            // m=0: sin=0, cos=1
    float sm = s1, cm = c1;
    #pragma unroll
    for (int m = 1; m < Mn; m++) {
        acc = fmaf(w[m], sm, acc);
        acc = fmaf(w[Mn + m], cm, acc);
        float sn = sm * c1 + cm * s1;
        cm = cm * c1 - sm * s1;
        sm = sn;
    }
    g_enc[idx] = acc + xt[idx];
}

// ---------------- kernel 4: collapsed decoder + head MLP, per batch ----------------
// grid 16, block 256. Queries are constant along N -> one softmax per (b,h).
__global__ void __launch_bounds__(256) k_decoder(const float* __restrict__ mask_token,
                                                 const float* __restrict__ dec_w,
                                                 const float* __restrict__ dec_b,
                                                 const float* __restrict__ fc1_w,
                                                 const float* __restrict__ fc1_g,
                                                 const float* __restrict__ fc1_b,
                                                 const float* __restrict__ fc2_w,
                                                 const float* __restrict__ fc2_g,
                                                 const float* __restrict__ fc2_b)
{
    __shared__ float mask_s[Cn];
    __shared__ float q_s[Cn];
    __shared__ float sc_s[Hn * Ln];
    __shared__ float xn_s[Cn];
    __shared__ float y1_s[Cn];
    const int b = blockIdx.x;
    const int t = threadIdx.x;

    mask_s[t] = mask_token[t];
    __syncthreads();

    // q_full = dec_w @ mask + dec_b (same for every n position)
    {
        float acc = dec_b[t];
        const float* wr = dec_w + t * Cn;
        #pragma unroll 8
        for (int j = 0; j < Cn; j++) acc = fmaf(wr[j], mask_s[j], acc);
        q_s[t] = acc;
    }
    __syncthreads();

    const int h = t >> 5, lane = t & 31;
    const float* erow = g_enc + (size_t)b * Cn * Ln + (h * HC + lane) * Ln;
    float e[Ln];
    #pragma unroll
    for (int i = 0; i < 16; i++) {
        float4 v = ((const float4*)erow)[i];
        e[4*i] = v.x; e[4*i+1] = v.y; e[4*i+2] = v.z; e[4*i+3] = v.w;
    }
    const float qv = q_s[h * HC + lane];

    // scores over latent positions l (warp reduce across channel lanes)
    #pragma unroll
    for (int l = 0; l < Ln; l++) {
        float p = qv * e[l];
        #pragma unroll
        for (int off = 16; off; off >>= 1) p += __shfl_xor_sync(0xffffffffu, p, off);
        if (lane == 0) sc_s[h * Ln + l] = p * SQRT32;
    }
    __syncwarp();

    // softmax over 64 within warp (2 values per lane)
    {
        float v0 = sc_s[h * Ln + lane];
        float v1 = sc_s[h * Ln + 32 + lane];
        float m = fmaxf(v0, v1);
        #pragma unroll
        for (int off = 16; off; off >>= 1) m = fmaxf(m, __shfl_xor_sync(0xffffffffu, m, off));
        float e0 = __expf(v0 - m), e1 = __expf(v1 - m);
        float s = e0 + e1;
        #pragma unroll
        for (int off = 16; off; off >>= 1) s += __shfl_xor_sync(0xffffffffu, s, off);
        float inv = 1.f / s;
        sc_s[h * Ln + lane]      = e0 * inv;
        sc_s[h * Ln + 32 + lane] = e1 * inv;
    }
    __syncwarp();

    // attention output + residual (mask)
    {
        float acc = 0.f;
        #pragma unroll
        for (int l = 0; l < Ln; l++) acc = fmaf(sc_s[h * Ln + l], e[l], acc);
        const int c = h * HC + lane;
        const float xn = acc + mask_s[c];
        xn_s[c] = xn;
        g_xncol[b * Cn + c] = xn;
    }
    __syncthreads();

    // fc1 + bn + leaky relu
    {
        float acc = 0.f;
        const float* wr = fc1_w + t * Cn;
        #pragma unroll 8
        for (int j = 0; j < Cn; j++) acc = fmaf(wr[j], xn_s[j], acc);
        float y = fc1_g[t] * acc * RS_BN + fc1_b[t];
        y1_s[t] = (y >= 0.f) ? y : 0.2f * y;
    }
    __syncthreads();

    // fc2 + bn + leaky relu (3 outputs)
    if (t < 3) {
        float acc = 0.f;
        const float* wr = fc2_w + t * Cn;
        #pragma unroll 8
        for (int j = 0; j < Cn; j++) acc = fmaf(wr[j], y1_s[j], acc);
        float y = fc2_g[t] * acc * RS_BN + fc2_b[t];
        g_y2[b * 3 + t] = (y >= 0.f) ? y : 0.2f * y;
    }
}

// ---------------- kernel 5: broadcast xn_pre (B,C,N) ----------------
__global__ void __launch_bounds__(256) k_bcast_xn(float4* __restrict__ out4)
{
    const int i = blockIdx.x * 256 + threadIdx.x;   // 0 .. 8388607 (float4 index)
    const float v = g_xncol[i >> 11];               // N/4 = 2048 float4 per (b,c)
    out4[i] = make_float4(v, v, v, v);
}

// ---------------- kernel 6: broadcast y (B,N,3) ----------------
__global__ void __launch_bounds__(256) k_bcast_y(float* __restrict__ out)
{
    const int idx = blockIdx.x * 256 + threadIdx.x; // 0 .. 393215
    const int b = idx / (Nn * 3);
    const int k = idx % 3;                          // N*3 divisible by 3
    out[(size_t)Bn * Cn * Nn + idx] = g_y2[b * 3 + k];
}

// ---------------- launch ----------------
extern "C" void kernel_launch(void* const* d_in, const int* in_sizes, int n_in,
                              void* d_out, int out_size)
{
    const float* xt        = (const float*)d_in[0];
    /* xn = d_in[1] is never read: fully masked path */
    const float* weights   = (const float*)d_in[2];
    const float* mask_tok  = (const float*)d_in[3];
    const float* enc_w     = (const float*)d_in[4];
    const float* enc_b     = (const float*)d_in[5];
    const float* dec_w     = (const float*)d_in[6];
    const float* dec_b     = (const float*)d_in[7];
    const float* fc1_w     = (const float*)d_in[8];
    const float* fc1_g     = (const float*)d_in[9];
    const float* fc1_b     = (const float*)d_in[10];
    const float* fc2_w     = (const float*)d_in[11];
    const float* fc2_g     = (const float*)d_in[12];
    const float* fc2_b     = (const float*)d_in[13];
    float* out = (float*)d_out;

    k_qkv<<<dim3(12, Bn), 256>>>(xt, enc_w, enc_b);
    k_attn<<<dim3(Hn, Bn), 64>>>();
    k_fourier<<<(Bn * Cn * Ln) / 256, 256>>>(xt, weights);
    k_decoder<<<Bn, 256>>>(mask_tok, dec_w, dec_b,
                           fc1_w, fc1_g, fc1_b, fc2_w, fc2_g, fc2_b);
    k_bcast_xn<<<(Bn * Cn * Nn / 4) / 256, 256>>>((float4*)out);
    k_bcast_y<<<(Bn * Nn * 3) / 256, 256>>>(out);
}

// round 4
// speedup vs baseline: 1.6723x; 1.6723x over previous
#include <cuda_runtime.h>
#include <math.h>

#define Bn 16
#define Cn 256
#define Ln 64
#define Nn 8192
#define Hn 8
#define HC 32          // C / H
#define Mn 12
#define SQRT32 5.656854249492381f
#define RS_BN 0.9999950000374997f   // 1/sqrt(1 + 1e-5)
#define PI_F 3.14159265358979323846f

// ---------------- scratch (device globals; no allocation) ----------------
__device__ float g_qkv[Bn * 3 * Cn * Ln];   // (B,3,C,L)
__device__ float g_xncol[Bn * Cn];          // xn_pre per (b,c) (const along n)
__device__ float g_y2[Bn * 3];              // head output per (b,k)

// ---------------- kernel 1: qkv = enc_w @ xt + enc_b ----------------
// grid (12, 16): 64-row tile x batch. block 256. micro-tile 4x4.
#define FMA4(acc, s, v) { acc.x = fmaf((s),(v).x,acc.x); acc.y = fmaf((s),(v).y,acc.y); \
                          acc.z = fmaf((s),(v).z,acc.z); acc.w = fmaf((s),(v).w,acc.w); }

__global__ void __launch_bounds__(256) k_qkv(const float* __restrict__ xt,
                                             const float* __restrict__ enc_w,
                                             const float* __restrict__ enc_b)
{
    __shared__ float4 xs4[128 * 16];   // 128 j-rows x 64 cols (as 16 float4) = 32KB
    const int b  = blockIdx.y;
    const int rt = blockIdx.x;               // row tile (64 rows)
    const float4* xb4 = (const float4*)(xt + b * Cn * Ln);

    const int rg = threadIdx.x >> 4;         // 0..15 -> rows rg*4..rg*4+3
    const int cg = threadIdx.x & 15;         // 0..15 -> cols cg*4..cg*4+3
    const int row0 = rt * 64 + rg * 4;

    const float4* w0p = (const float4*)(enc_w + (row0 + 0) * Cn);
    const float4* w1p = (const float4*)(enc_w + (row0 + 1) * Cn);
    const float4* w2p = (const float4*)(enc_w + (row0 + 2) * Cn);
    const float4* w3p = (const float4*)(enc_w + (row0 + 3) * Cn);

    float4 acc0 = {0,0,0,0}, acc1 = {0,0,0,0}, acc2 = {0,0,0,0}, acc3 = {0,0,0,0};

    for (int jc = 0; jc < 2; jc++) {
        for (int i = threadIdx.x; i < 2048; i += 256) xs4[i] = xb4[jc * 2048 + i];
        __syncthreads();
        #pragma unroll 8
        for (int j4 = 0; j4 < 32; j4++) {
            const int jg = jc * 32 + j4;
            float4 w0 = w0p[jg], w1 = w1p[jg], w2 = w2p[jg], w3 = w3p[jg];
            float4 xa = xs4[(j4 * 4 + 0) * 16 + cg];
            float4 xb = xs4[(j4 * 4 + 1) * 16 + cg];
            float4 xc = xs4[(j4 * 4 + 2) * 16 + cg];
            float4 xd = xs4[(j4 * 4 + 3) * 16 + cg];
            FMA4(acc0, w0.x, xa); FMA4(acc0, w0.y, xb); FMA4(acc0, w0.z, xc); FMA4(acc0, w0.w, xd);
            FMA4(acc1, w1.x, xa); FMA4(acc1, w1.y, xb); FMA4(acc1, w1.z, xc); FMA4(acc1, w1.w, xd);
            FMA4(acc2, w2.x, xa); FMA4(acc2, w2.y, xb); FMA4(acc2, w2.z, xc); FMA4(acc2, w2.w, xd);
            FMA4(acc3, w3.x, xa); FMA4(acc3, w3.y, xb); FMA4(acc3, w3.z, xc); FMA4(acc3, w3.w, xd);
        }
        __syncthreads();
    }

    float4 accs[4] = {acc0, acc1, acc2, acc3};
    #pragma unroll
    for (int r = 0; r < 4; r++) {
        const int o = row0 + r;
        const float bias = enc_b[o];
        float4 res = accs[r];
        res.x += bias; res.y += bias; res.z += bias; res.w += bias;
        ((float4*)(g_qkv + (size_t)b * 3 * Cn * Ln + o * Ln))[cg] = res;
    }
}

// ---------------- kernel 2: fused enc-attn + fourier + decoder-attn ----------------
// grid (H, B), block 64. Each block owns one (b,h) slice end-to-end; the encoder
// output slice stays in smem (never hits global), decoder softmax is per-head.
__global__ void __launch_bounds__(64) k_fused(const float* __restrict__ xt,
                                              const float* __restrict__ weights,
                                              const float* __restrict__ mask_token,
                                              const float* __restrict__ dec_w,
                                              const float* __restrict__ dec_b)
{
    __shared__ float ks[64 * 33];       // K[s][c]
    __shared__ float vs[64 * 33];       // V[s][c]
    __shared__ float sc[64 * 65];       // per-l score row (encoder softmax)
    __shared__ float es[HC * 65];       // encoder output slice [c][l], padded
    __shared__ float ws[HC * 24];       // fourier weights for this head's channels
    __shared__ float mask_s[Cn];
    __shared__ float q_s[HC];           // decoder q for this head
    __shared__ float p_s[Ln];           // decoder softmax probs

    const int h = blockIdx.x, b = blockIdx.y;
    const int t = threadIdx.x;
    const float* qb = g_qkv + (size_t)b * 3 * Cn * Ln + (h * HC) * Ln;
    const float* kb = qb + Cn * Ln;
    const float* vb = qb + 2 * Cn * Ln;

    // stage K,V (transposed), mask, fourier weights
    for (int i = t; i < 2048; i += 64) {
        int cc = i >> 6, s = i & 63;
        ks[s * 33 + cc] = kb[cc * Ln + s];
        vs[s * 33 + cc] = vb[cc * Ln + s];
    }
    #pragma unroll
    for (int i = 0; i < 4; i++) mask_s[t + i * 64] = mask_token[t + i * 64];
    for (int i = t; i < HC * 24; i += 64) {
        int cc = i / 24, m = i - cc * 24;
        ws[i] = weights[(h * HC + cc) * 24 + m];
    }
    __syncthreads();

    // ---- encoder attention (thread-per-query l) ----
    const int l = t;
    float q[HC];
    #pragma unroll
    for (int cc = 0; cc < HC; cc++) q[cc] = qb[cc * Ln + l];

    float mx = -1e30f;
    for (int s = 0; s < 64; s++) {
        float d = 0.f;
        #pragma unroll
        for (int cc = 0; cc < HC; cc++) d = fmaf(q[cc], ks[s * 33 + cc], d);
        d *= SQRT32;
        sc[l * 65 + s] = d;
        mx = fmaxf(mx, d);
    }
    float sum = 0.f;
    for (int s = 0; s < 64; s++) {
        float e = __expf(sc[l * 65 + s] - mx);
        sc[l * 65 + s] = e;
        sum += e;
    }
    const float inv = 1.f / sum;
    float acc[HC];
    #pragma unroll
    for (int cc = 0; cc < HC; cc++) acc[cc] = 0.f;
    for (int s = 0; s < 64; s++) {
        float p = sc[l * 65 + s];
        #pragma unroll
        for (int cc = 0; cc < HC; cc++) acc[cc] = fmaf(p, vs[s * 33 + cc], acc[cc]);
    }

    // ---- fourier basis + residual -> es[c][l] (stays in smem) ----
    const float* xrow = xt + (size_t)b * Cn * Ln + (h * HC) * Ln;
    #pragma unroll
    for (int cc = 0; cc < HC; cc++) {
        const float a = acc[cc] * inv;
        const float phi = a * (PI_F / (float)Mn);
        float s1, c1;
        __sincosf(phi, &s1, &c1);
        const float* w = ws + cc * 24;
        float fv = w[Mn];                 // m=0: sin=0, cos=1
        float sm = s1, cm = c1;
        #pragma unroll
        for (int m = 1; m < Mn; m++) {
            fv = fmaf(w[m], sm, fv);
            fv = fmaf(w[Mn + m], cm, fv);
            float sn = sm * c1 + cm * s1;
            cm = cm * c1 - sm * s1;
            sm = sn;
        }
        es[cc * 65 + l] = fv + xrow[cc * Ln + l];
    }
    __syncthreads();

    // ---- decoder q for this head: q[c] = dec_w[row,:] @ mask + dec_b[row] ----
    {
        const int c = t >> 1, part = t & 1;          // 2 threads per row
        const int row = h * HC + c;
        const float4* wp = (const float4*)(dec_w + row * Cn) + part * 32;
        const float4* mp = (const float4*)(mask_s) + part * 32;
        float a2 = 0.f;
        #pragma unroll 8
        for (int i = 0; i < 32; i++) {
            float4 w4 = wp[i], m4 = mp[i];
            a2 = fmaf(w4.x, m4.x, a2); a2 = fmaf(w4.y, m4.y, a2);
            a2 = fmaf(w4.z, m4.z, a2); a2 = fmaf(w4.w, m4.w, a2);
        }
        a2 += __shfl_xor_sync(0xffffffffu, a2, 1);
        if (part == 0) q_s[c] = a2 + dec_b[row];
    }
    __syncthreads();

    // ---- decoder scores over latent l ----
    {
        float d = 0.f;
        #pragma unroll
        for (int cc = 0; cc < HC; cc++) d = fmaf(q_s[cc], es[cc * 65 + l], d);
        p_s[l] = d * SQRT32;
    }
    __syncthreads();

    // ---- decoder softmax (warp 0 handles all 64) ----
    if (t < 32) {
        float v0 = p_s[t], v1 = p_s[t + 32];
        float m = fmaxf(v0, v1);
        #pragma unroll
        for (int off = 16; off; off >>= 1) m = fmaxf(m, __shfl_xor_sync(0xffffffffu, m, off));
        float e0 = __expf(v0 - m), e1 = __expf(v1 - m);
        float s = e0 + e1;
        #pragma unroll
        for (int off = 16; off; off >>= 1) s += __shfl_xor_sync(0xffffffffu, s, off);
        float pin = 1.f / s;
        p_s[t]      = e0 * pin;
        p_s[t + 32] = e1 * pin;
    }
    __syncthreads();

    // ---- decoder output + mask residual -> g_xncol ----
    if (t < HC) {
        const int c = t;
        float a3 = 0.f;
        #pragma unroll
        for (int ll = 0; ll < Ln; ll++) a3 = fmaf(p_s[ll], es[c * 65 + ll], a3);
        g_xncol[b * Cn + h * HC + c] = a3 + mask_s[h * HC + c];
    }
}

// ---------------- kernel 3: head MLP (fc1+bn+lrelu, fc2+bn+lrelu) ----------------
__global__ void __launch_bounds__(256) k_head(const float* __restrict__ fc1_w,
                                              const float* __restrict__ fc1_g,
                                              const float* __restrict__ fc1_b,
                                              const float* __restrict__ fc2_w,
                                              const float* __restrict__ fc2_g,
                                              const float* __restrict__ fc2_b)
{
    __shared__ float xn_s[Cn];
    __shared__ float y1_s[Cn];
    const int b = blockIdx.x;
    const int t = threadIdx.x;

    xn_s[t] = g_xncol[b * Cn + t];
    __syncthreads();

    {
        float acc = 0.f;
        const float4* wr = (const float4*)(fc1_w + t * Cn);
        const float4* xr = (const float4*)xn_s;
        #pragma unroll 8
        for (int i = 0; i < 64; i++) {
            float4 w4 = wr[i], x4 = xr[i];
            acc = fmaf(w4.x, x4.x, acc); acc = fmaf(w4.y, x4.y, acc);
            acc = fmaf(w4.z, x4.z, acc); acc = fmaf(w4.w, x4.w, acc);
        }
        float y = fc1_g[t] * acc * RS_BN + fc1_b[t];
        y1_s[t] = (y >= 0.f) ? y : 0.2f * y;
    }
    __syncthreads();

    // fc2: 3 warps, warp w -> output row w
    const int w = t >> 5, lane = t & 31;
    if (w < 3) {
        const float4* wr = (const float4*)(fc2_w + w * Cn) + lane * 2;
        const float4* yr = (const float4*)y1_s + lane * 2;
        float acc = 0.f;
        #pragma unroll
        for (int i = 0; i < 2; i++) {
            float4 w4 = wr[i], y4 = yr[i];
            acc = fmaf(w4.x, y4.x, acc); acc = fmaf(w4.y, y4.y, acc);
            acc = fmaf(w4.z, y4.z, acc); acc = fmaf(w4.w, y4.w, acc);
        }
        #pragma unroll
        for (int off = 16; off; off >>= 1) acc += __shfl_xor_sync(0xffffffffu, acc, off);
        if (lane == 0) {
            float y = fc2_g[w] * acc * RS_BN + fc2_b[w];
            g_y2[b * 3 + w] = (y >= 0.f) ? y : 0.2f * y;
        }
    }
}

// ---------------- kernel 4: broadcast xn_pre (B,C,N) ----------------
__global__ void __launch_bounds__(256) k_bcast_xn(float4* __restrict__ out4)
{
    const int i = blockIdx.x * 256 + threadIdx.x;   // float4 index
    const float v = g_xncol[i >> 11];               // N/4 = 2048 float4 per (b,c)
    out4[i] = make_float4(v, v, v, v);
}

// ---------------- kernel 5: broadcast y (B,N,3) ----------------
__global__ void __launch_bounds__(256) k_bcast_y(float* __restrict__ out)
{
    const int idx = blockIdx.x * 256 + threadIdx.x; // 0 .. 393215
    const int b = idx / (Nn * 3);
    const int k = idx % 3;
    out[(size_t)Bn * Cn * Nn + idx] = g_y2[b * 3 + k];
}

// ---------------- launch ----------------
extern "C" void kernel_launch(void* const* d_in, const int* in_sizes, int n_in,
                              void* d_out, int out_size)
{
    const float* xt        = (const float*)d_in[0];
    /* xn = d_in[1] never read: fully-masked path */
    const float* weights   = (const float*)d_in[2];
    const float* mask_tok  = (const float*)d_in[3];
    const float* enc_w     = (const float*)d_in[4];
    const float* enc_b     = (const float*)d_in[5];
    const float* dec_w     = (const float*)d_in[6];
    const float* dec_b     = (const float*)d_in[7];
    const float* fc1_w     = (const float*)d_in[8];
    const float* fc1_g     = (const float*)d_in[9];
    const float* fc1_b     = (const float*)d_in[10];
    const float* fc2_w     = (const float*)d_in[11];
    const float* fc2_g     = (const float*)d_in[12];
    const float* fc2_b     = (const float*)d_in[13];
    float* out = (float*)d_out;

    k_qkv  <<<dim3(12, Bn), 256>>>(xt, enc_w, enc_b);
    k_fused<<<dim3(Hn, Bn), 64>>>(xt, weights, mask_tok, dec_w, dec_b);
    k_head <<<Bn, 256>>>(fc1_w, fc1_g, fc1_b, fc2_w, fc2_g, fc2_b);
    k_bcast_xn<<<(Bn * Cn * Nn / 4) / 256, 256>>>((float4*)out);
    k_bcast_y <<<(Bn * Nn * 3) / 256, 256>>>(out);
}

// round 7
// speedup vs baseline: 2.0676x; 1.2364x over previous
#include <cuda_runtime.h>
#include <math.h>

#define Bn 16
#define Cn 256
#define Ln 64
#define Nn 8192
#define Hn 8
#define HC 32          // C / H
#define Mn 12
#define SQRT32 5.656854249492381f
#define RS_BN 0.9999950000374997f   // 1/sqrt(1 + 1e-5)
#define PI_F 3.14159265358979323846f

// ---------------- scratch (device globals; no allocation) ----------------
__device__ float g_qkv[Bn * 3 * Cn * Ln];   // (B,3,C,L)
__device__ float g_xncol[Bn * Cn];          // xn_pre per (b,c) (const along n)
__device__ float g_y2[Bn * 3];              // head output per (b,k)

// ---------------- kernel 1: qkv = enc_w @ xt + enc_b ----------------
#define FMA4(acc, s, v) { acc.x = fmaf((s),(v).x,acc.x); acc.y = fmaf((s),(v).y,acc.y); \
                          acc.z = fmaf((s),(v).z,acc.z); acc.w = fmaf((s),(v).w,acc.w); }

__global__ void __launch_bounds__(256) k_qkv(const float* __restrict__ xt,
                                             const float* __restrict__ enc_w,
                                             const float* __restrict__ enc_b)
{
    __shared__ float4 xs4[128 * 16];
    const int b  = blockIdx.y;
    const int rt = blockIdx.x;
    const float4* xb4 = (const float4*)(xt + b * Cn * Ln);

    const int rg = threadIdx.x >> 4;
    const int cg = threadIdx.x & 15;
    const int row0 = rt * 64 + rg * 4;

    const float4* w0p = (const float4*)(enc_w + (row0 + 0) * Cn);
    const float4* w1p = (const float4*)(enc_w + (row0 + 1) * Cn);
    const float4* w2p = (const float4*)(enc_w + (row0 + 2) * Cn);
    const float4* w3p = (const float4*)(enc_w + (row0 + 3) * Cn);

    float4 acc0 = {0,0,0,0}, acc1 = {0,0,0,0}, acc2 = {0,0,0,0}, acc3 = {0,0,0,0};

    for (int jc = 0; jc < 2; jc++) {
        for (int i = threadIdx.x; i < 2048; i += 256) xs4[i] = xb4[jc * 2048 + i];
        __syncthreads();
        #pragma unroll 8
        for (int j4 = 0; j4 < 32; j4++) {
            const int jg = jc * 32 + j4;
            float4 w0 = w0p[jg], w1 = w1p[jg], w2 = w2p[jg], w3 = w3p[jg];
            float4 xa = xs4[(j4 * 4 + 0) * 16 + cg];
            float4 xb = xs4[(j4 * 4 + 1) * 16 + cg];
            float4 xc = xs4[(j4 * 4 + 2) * 16 + cg];
            float4 xd = xs4[(j4 * 4 + 3) * 16 + cg];
            FMA4(acc0, w0.x, xa); FMA4(acc0, w0.y, xb); FMA4(acc0, w0.z, xc); FMA4(acc0, w0.w, xd);
            FMA4(acc1, w1.x, xa); FMA4(acc1, w1.y, xb); FMA4(acc1, w1.z, xc); FMA4(acc1, w1.w, xd);
            FMA4(acc2, w2.x, xa); FMA4(acc2, w2.y, xb); FMA4(acc2, w2.z, xc); FMA4(acc2, w2.w, xd);
            FMA4(acc3, w3.x, xa); FMA4(acc3, w3.y, xb); FMA4(acc3, w3.z, xc); FMA4(acc3, w3.w, xd);
        }
        __syncthreads();
    }

    float4 accs[4] = {acc0, acc1, acc2, acc3};
    #pragma unroll
    for (int r = 0; r < 4; r++) {
        const int o = row0 + r;
        const float bias = enc_b[o];
        float4 res = accs[r];
        res.x += bias; res.y += bias; res.z += bias; res.w += bias;
        ((float4*)(g_qkv + (size_t)b * 3 * Cn * Ln + o * Ln))[cg] = res;
    }
}

// ---------------- kernel 2: fused enc-attn + fourier + dec-attn ----------------
// grid (H, B), block 256. Warp w covers l = w*8 + (lane>>2), g = lane&3.
// Score pass: g splits the 64 s positions (16 each, full 32-ch dot).
// Weighted-V / fourier pass: g splits channels (8 each).
// Q is read directly from global into registers (no smem staging) to fit 48KB.
__global__ void __launch_bounds__(256) k_fused(const float* __restrict__ xt,
                                               const float* __restrict__ weights,
                                               const float* __restrict__ mask_token,
                                               const float* __restrict__ dec_w,
                                               const float* __restrict__ dec_b)
{
    __shared__ float ks[64 * 33];       // K[s][c]
    __shared__ float vs[64 * 33];       // V[s][c]
    __shared__ float sc[64 * 65];       // exp-scores per l
    __shared__ float es[HC * 65];       // encoder-out slice [c][l]
    __shared__ float ws[HC * 24];
    __shared__ float mask_s[Cn];
    __shared__ float q_s[HC];
    __shared__ float p_s[Ln];
    // total: 8448+8448+16640+8320+3072+1024+128+256 = 46336 B < 48KB

    const int h = blockIdx.x, b = blockIdx.y;
    const int t = threadIdx.x;
    const int lane = t & 31;
    const int l = (t >> 5) * 8 + (lane >> 2);
    const int g = lane & 3;
    const float* qb = g_qkv + (size_t)b * 3 * Cn * Ln + (h * HC) * Ln;
    const float* kb = qb + Cn * Ln;
    const float* vb = qb + 2 * Cn * Ln;

    for (int i = t; i < 2048; i += 256) {
        int cc = i >> 6, s = i & 63;
        ks[s * 33 + cc] = kb[cc * Ln + s];
        vs[s * 33 + cc] = vb[cc * Ln + s];
    }
    mask_s[t] = mask_token[t];
    for (int i = t; i < HC * 24; i += 256) {
        int cc = i / 24, m = i - cc * 24;
        ws[i] = weights[(h * HC + cc) * 24 + m];
    }

    // q vector straight from global (L2-hot; 4-thread broadcast per address)
    float q[HC];
    #pragma unroll
    for (int cc = 0; cc < HC; cc++) q[cc] = __ldg(qb + cc * Ln + l);
    __syncthreads();

    // ---- scores: this thread handles s = g, g+4, ..., g+60 ----
    float dloc[16];
    float mx = -1e30f;
    #pragma unroll
    for (int i = 0; i < 16; i++) {
        const int s = g + i * 4;
        float d = 0.f;
        #pragma unroll
        for (int cc = 0; cc < HC; cc++) d = fmaf(q[cc], ks[s * 33 + cc], d);
        d *= SQRT32;
        dloc[i] = d;
        mx = fmaxf(mx, d);
    }
    mx = fmaxf(mx, __shfl_xor_sync(0xffffffffu, mx, 1));
    mx = fmaxf(mx, __shfl_xor_sync(0xffffffffu, mx, 2));

    float sum = 0.f;
    #pragma unroll
    for (int i = 0; i < 16; i++) {
        const int s = g + i * 4;
        float e = __expf(dloc[i] - mx);
        sc[l * 65 + s] = e;
        sum += e;
    }
    sum += __shfl_xor_sync(0xffffffffu, sum, 1);
    sum += __shfl_xor_sync(0xffffffffu, sum, 2);
    const float inv = 1.f / sum;
    __syncwarp();

    // ---- weighted V (this thread owns channels g*8 .. g*8+7) ----
    float acc[8];
    #pragma unroll
    for (int j = 0; j < 8; j++) acc[j] = 0.f;
    for (int s = 0; s < 64; s++) {
        const float p = sc[l * 65 + s];
        #pragma unroll
        for (int j = 0; j < 8; j++) acc[j] = fmaf(p, vs[s * 33 + g * 8 + j], acc[j]);
    }

    // ---- fourier + residual -> es ----
    const float* xrow = xt + (size_t)b * Cn * Ln + (h * HC) * Ln;
    #pragma unroll
    for (int j = 0; j < 8; j++) {
        const int cc = g * 8 + j;
        const float a = acc[j] * inv;
        const float phi = a * (PI_F / (float)Mn);
        float s1, c1;
        __sincosf(phi, &s1, &c1);
        const float* w = ws + cc * 24;
        float fv = w[Mn];
        float sm = s1, cm = c1;
        #pragma unroll
        for (int m = 1; m < Mn; m++) {
            fv = fmaf(w[m], sm, fv);
            fv = fmaf(w[Mn + m], cm, fv);
            float sn = sm * c1 + cm * s1;
            cm = cm * c1 - sm * s1;
            sm = sn;
        }
        es[cc * 65 + l] = fv + xrow[cc * Ln + l];
    }

    // ---- decoder q: 8 threads per output row, 32-elem chunks ----
    {
        const int c = t >> 3, part = t & 7;
        const int row = h * HC + c;
        const float4* wp = (const float4*)(dec_w + row * Cn) + part * 8;
        const float4* mp = (const float4*)(mask_s) + part * 8;
        float a2 = 0.f;
        #pragma unroll
        for (int i = 0; i < 8; i++) {
            float4 w4 = wp[i], m4 = mp[i];
            a2 = fmaf(w4.x, m4.x, a2); a2 = fmaf(w4.y, m4.y, a2);
            a2 = fmaf(w4.z, m4.z, a2); a2 = fmaf(w4.w, m4.w, a2);
        }
        a2 += __shfl_xor_sync(0xffffffffu, a2, 1);
        a2 += __shfl_xor_sync(0xffffffffu, a2, 2);
        a2 += __shfl_xor_sync(0xffffffffu, a2, 4);
        if (part == 0) q_s[c] = a2 + dec_b[row];
    }
    __syncthreads();

    // ---- decoder scores over latent l ----
    if (t < Ln) {
        float d = 0.f;
        #pragma unroll
        for (int cc = 0; cc < HC; cc++) d = fmaf(q_s[cc], es[cc * 65 + t], d);
        p_s[t] = d * SQRT32;
    }
    __syncthreads();

    if (t < 32) {
        float v0 = p_s[t], v1 = p_s[t + 32];
        float m = fmaxf(v0, v1);
        #pragma unroll
        for (int off = 16; off; off >>= 1) m = fmaxf(m, __shfl_xor_sync(0xffffffffu, m, off));
        float e0 = __expf(v0 - m), e1 = __expf(v1 - m);
        float s = e0 + e1;
        #pragma unroll
        for (int off = 16; off; off >>= 1) s += __shfl_xor_sync(0xffffffffu, s, off);
        float pin = 1.f / s;
        p_s[t]      = e0 * pin;
        p_s[t + 32] = e1 * pin;
    }
    __syncthreads();

    if (t < HC) {
        float a3 = 0.f;
        #pragma unroll
        for (int ll = 0; ll < Ln; ll++) a3 = fmaf(p_s[ll], es[t * 65 + ll], a3);
        g_xncol[b * Cn + h * HC + t] = a3 + mask_s[h * HC + t];
    }
}

// ---------------- kernel 3: head MLP ----------------
__global__ void __launch_bounds__(256) k_head(const float* __restrict__ fc1_w,
                                              const float* __restrict__ fc1_g,
                                              const float* __restrict__ fc1_b,
                                              const float* __restrict__ fc2_w,
                                              const float* __restrict__ fc2_g,
                                              const float* __restrict__ fc2_b)
{
    __shared__ float xn_s[Cn];
    __shared__ float y1_s[Cn];
    const int b = blockIdx.x;
    const int t = threadIdx.x;

    xn_s[t] = g_xncol[b * Cn + t];
    __syncthreads();

    {
        float acc = 0.f;
        const float4* wr = (const float4*)(fc1_w + t * Cn);
        const float4* xr = (const float4*)xn_s;
        #pragma unroll 8
        for (int i = 0; i < 64; i++) {
            float4 w4 = wr[i], x4 = xr[i];
            acc = fmaf(w4.x, x4.x, acc); acc = fmaf(w4.y, x4.y, acc);
            acc = fmaf(w4.z, x4.z, acc); acc = fmaf(w4.w, x4.w, acc);
        }
        float y = fc1_g[t] * acc * RS_BN + fc1_b[t];
        y1_s[t] = (y >= 0.f) ? y : 0.2f * y;
    }
    __syncthreads();

    const int w = t >> 5, lane = t & 31;
    if (w < 3) {
        const float4* wr = (const float4*)(fc2_w + w * Cn) + lane * 2;
        const float4* yr = (const float4*)y1_s + lane * 2;
        float acc = 0.f;
        #pragma unroll
        for (int i = 0; i < 2; i++) {
            float4 w4 = wr[i], y4 = yr[i];
            acc = fmaf(w4.x, y4.x, acc); acc = fmaf(w4.y, y4.y, acc);
            acc = fmaf(w4.z, y4.z, acc); acc = fmaf(w4.w, y4.w, acc);
        }
        #pragma unroll
        for (int off = 16; off; off >>= 1) acc += __shfl_xor_sync(0xffffffffu, acc, off);
        if (lane == 0) {
            float y = fc2_g[w] * acc * RS_BN + fc2_b[w];
            g_y2[b * 3 + w] = (y >= 0.f) ? y : 0.2f * y;
        }
    }
}

// ---------------- kernel 4: merged broadcast (xn + y) ----------------
// Blocks 0..511: warp-per-(b,c)-row, 64 streaming float4 stores per lane.
// Blocks 512..527: y rows, cyclic float4 pattern per batch.
__global__ void __launch_bounds__(256) k_bcast(float4* __restrict__ out4)
{
    const int t = threadIdx.x;
    if (blockIdx.x < 512) {
        const int warp = t >> 5, lane = t & 31;
        const int row = blockIdx.x * 8 + warp;          // b*Cn + c
        const float v = g_xncol[row];
        const float4 v4 = make_float4(v, v, v, v);
        float4* p = out4 + (size_t)row * 2048 + lane;
        #pragma unroll 16
        for (int i = 0; i < 64; i++) __stcs(p + i * 32, v4);
    } else {
        const int b = blockIdx.x - 512;
        const float y0 = g_y2[b * 3 + 0];
        const float y1 = g_y2[b * 3 + 1];
        const float y2 = g_y2[b * 3 + 2];
        float4 var[3];
        var[0] = make_float4(y0, y1, y2, y0);
        var[1] = make_float4(y1, y2, y0, y1);
        var[2] = make_float4(y2, y0, y1, y2);
        float4* p = out4 + (size_t)(Bn * Cn * Nn) / 4 + (size_t)b * 6144;
        for (int i = t; i < 6144; i += 256) __stcs(p + i, var[i % 3]);
    }
}

// ---------------- launch ----------------
extern "C" void kernel_launch(void* const* d_in, const int* in_sizes, int n_in,
                              void* d_out, int out_size)
{
    const float* xt        = (const float*)d_in[0];
    /* xn = d_in[1] never read: fully-masked path */
    const float* weights   = (const float*)d_in[2];
    const float* mask_tok  = (const float*)d_in[3];
    const float* enc_w     = (const float*)d_in[4];
    const float* enc_b     = (const float*)d_in[5];
    const float* dec_w     = (const float*)d_in[6];
    const float* dec_b     = (const float*)d_in[7];
    const float* fc1_w     = (const float*)d_in[8];
    const float* fc1_g     = (const float*)d_in[9];
    const float* fc1_b     = (const float*)d_in[10];
    const float* fc2_w     = (const float*)d_in[11];
    const float* fc2_g     = (const float*)d_in[12];
    const float* fc2_b     = (const float*)d_in[13];
    float* out = (float*)d_out;

    k_qkv  <<<dim3(12, Bn), 256>>>(xt, enc_w, enc_b);
    k_fused<<<dim3(Hn, Bn), 256>>>(xt, weights, mask_tok, dec_w, dec_b);
    k_head <<<Bn, 256>>>(fc1_w, fc1_g, fc1_b, fc2_w, fc2_g, fc2_b);
    k_bcast<<<528, 256>>>((float4*)out);
}

// round 8
// speedup vs baseline: 2.0798x; 1.0059x over previous
#include <cuda_runtime.h>
#include <math.h>

#define Bn 16
#define Cn 256
#define Ln 64
#define Nn 8192
#define Hn 8
#define HC 32          // C / H
#define Mn 12
#define SQRT32 5.656854249492381f
#define RS_BN 0.9999950000374997f   // 1/sqrt(1 + 1e-5)
#define PI_F 3.14159265358979323846f

// ---------------- scratch (device globals; no allocation) ----------------
__device__ float g_qkv[Bn * 3 * Cn * Ln];   // (B,3,C,L)
__device__ float g_xncol[Bn * Cn];          // xn_pre per (b,c) (const along n)

// ---------------- kernel 1: qkv = enc_w @ xt + enc_b ----------------
// grid (24, 16): 32-row tiles x batch. block 256, micro-tile 2x4.
#define FMA4(acc, s, v) { acc.x = fmaf((s),(v).x,acc.x); acc.y = fmaf((s),(v).y,acc.y); \
                          acc.z = fmaf((s),(v).z,acc.z); acc.w = fmaf((s),(v).w,acc.w); }

__global__ void __launch_bounds__(256) k_qkv(const float* __restrict__ xt,
                                             const float* __restrict__ enc_w,
                                             const float* __restrict__ enc_b)
{
    __shared__ float4 xs4[128 * 16];   // 128 j-rows x 64 cols = 32KB
    const int b  = blockIdx.y;
    const int rt = blockIdx.x;               // 32-row tile
    const float4* xb4 = (const float4*)(xt + b * Cn * Ln);

    const int rg = threadIdx.x >> 4;         // 0..15 -> rows rg*2, rg*2+1
    const int cg = threadIdx.x & 15;         // 0..15 -> cols cg*4..cg*4+3
    const int row0 = rt * 32 + rg * 2;

    const float4* w0p = (const float4*)(enc_w + (row0 + 0) * Cn);
    const float4* w1p = (const float4*)(enc_w + (row0 + 1) * Cn);

    float4 acc0 = {0,0,0,0}, acc1 = {0,0,0,0};

    for (int jc = 0; jc < 2; jc++) {
        for (int i = threadIdx.x; i < 2048; i += 256) xs4[i] = xb4[jc * 2048 + i];
        __syncthreads();
        #pragma unroll 8
        for (int j4 = 0; j4 < 32; j4++) {
            const int jg = jc * 32 + j4;
            float4 w0 = w0p[jg], w1 = w1p[jg];
            float4 xa = xs4[(j4 * 4 + 0) * 16 + cg];
            float4 xb = xs4[(j4 * 4 + 1) * 16 + cg];
            float4 xc = xs4[(j4 * 4 + 2) * 16 + cg];
            float4 xd = xs4[(j4 * 4 + 3) * 16 + cg];
            FMA4(acc0, w0.x, xa); FMA4(acc0, w0.y, xb); FMA4(acc0, w0.z, xc); FMA4(acc0, w0.w, xd);
            FMA4(acc1, w1.x, xa); FMA4(acc1, w1.y, xb); FMA4(acc1, w1.z, xc); FMA4(acc1, w1.w, xd);
        }
        __syncthreads();
    }

    {
        const float b0 = enc_b[row0], b1 = enc_b[row0 + 1];
        acc0.x += b0; acc0.y += b0; acc0.z += b0; acc0.w += b0;
        acc1.x += b1; acc1.y += b1; acc1.z += b1; acc1.w += b1;
        float4* outp = (float4*)(g_qkv + (size_t)b * 3 * Cn * Ln + row0 * Ln);
        outp[cg] = acc0;
        outp[16 + cg] = acc1;
    }
}

// ---------------- kernel 2: fused enc-attn + fourier + dec-attn ----------------
// grid (H, B), block 256. Warp w covers l = w*8 + (lane>>2), g = lane&3.
__global__ void __launch_bounds__(256) k_fused(const float* __restrict__ xt,
                                               const float* __restrict__ weights,
                                               const float* __restrict__ mask_token,
                                               const float* __restrict__ dec_w,
                                               const float* __restrict__ dec_b)
{
    __shared__ float ks[64 * 33];       // K[s][c]
    __shared__ float vs[64 * 33];       // V[s][c]
    __shared__ float sc[64 * 65];       // exp-scores per l
    __shared__ float es[HC * 65];       // encoder-out slice [c][l]
    __shared__ float ws[HC * 24];
    __shared__ float mask_s[Cn];
    __shared__ float q_s[HC];
    __shared__ float p_s[Ln];
    // total 46336 B < 48KB

    const int h = blockIdx.x, b = blockIdx.y;
    const int t = threadIdx.x;
    const int lane = t & 31;
    const int l = (t >> 5) * 8 + (lane >> 2);
    const int g = lane & 3;
    const float* qb = g_qkv + (size_t)b * 3 * Cn * Ln + (h * HC) * Ln;
    const float* kb = qb + Cn * Ln;
    const float* vb = qb + 2 * Cn * Ln;

    for (int i = t; i < 2048; i += 256) {
        int cc = i >> 6, s = i & 63;
        ks[s * 33 + cc] = kb[cc * Ln + s];
        vs[s * 33 + cc] = vb[cc * Ln + s];
    }
    mask_s[t] = mask_token[t];
    for (int i = t; i < HC * 24; i += 256) {
        int cc = i / 24, m = i - cc * 24;
        ws[i] = weights[(h * HC + cc) * 24 + m];
    }

    float q[HC];
    #pragma unroll
    for (int cc = 0; cc < HC; cc++) q[cc] = __ldg(qb + cc * Ln + l);
    __syncthreads();

    // ---- scores: this thread handles s = g, g+4, ..., g+60 ----
    float dloc[16];
    float mx = -1e30f;
    #pragma unroll
    for (int i = 0; i < 16; i++) {
        const int s = g + i * 4;
        float d = 0.f;
        #pragma unroll
        for (int cc = 0; cc < HC; cc++) d = fmaf(q[cc], ks[s * 33 + cc], d);
        d *= SQRT32;
        dloc[i] = d;
        mx = fmaxf(mx, d);
    }
    mx = fmaxf(mx, __shfl_xor_sync(0xffffffffu, mx, 1));
    mx = fmaxf(mx, __shfl_xor_sync(0xffffffffu, mx, 2));

    float sum = 0.f;
    #pragma unroll
    for (int i = 0; i < 16; i++) {
        const int s = g + i * 4;
        float e = __expf(dloc[i] - mx);
        sc[l * 65 + s] = e;
        sum += e;
    }
    sum += __shfl_xor_sync(0xffffffffu, sum, 1);
    sum += __shfl_xor_sync(0xffffffffu, sum, 2);
    const float inv = 1.f / sum;
    __syncwarp();

    // ---- weighted V (channels g*8 .. g*8+7) ----
    float acc[8];
    #pragma unroll
    for (int j = 0; j < 8; j++) acc[j] = 0.f;
    for (int s = 0; s < 64; s++) {
        const float p = sc[l * 65 + s];
        #pragma unroll
        for (int j = 0; j < 8; j++) acc[j] = fmaf(p, vs[s * 33 + g * 8 + j], acc[j]);
    }

    // ---- fourier + residual -> es ----
    const float* xrow = xt + (size_t)b * Cn * Ln + (h * HC) * Ln;
    #pragma unroll
    for (int j = 0; j < 8; j++) {
        const int cc = g * 8 + j;
        const float a = acc[j] * inv;
        const float phi = a * (PI_F / (float)Mn);
        float s1, c1;
        __sincosf(phi, &s1, &c1);
        const float* w = ws + cc * 24;
        float fv = w[Mn];
        float sm = s1, cm = c1;
        #pragma unroll
        for (int m = 1; m < Mn; m++) {
            fv = fmaf(w[m], sm, fv);
            fv = fmaf(w[Mn + m], cm, fv);
            float sn = sm * c1 + cm * s1;
            cm = cm * c1 - sm * s1;
            sm = sn;
        }
        es[cc * 65 + l] = fv + xrow[cc * Ln + l];
    }

    // ---- decoder q: 8 threads per output row ----
    {
        const int c = t >> 3, part = t & 7;
        const int row = h * HC + c;
        const float4* wp = (const float4*)(dec_w + row * Cn) + part * 8;
        const float4* mp = (const float4*)(mask_s) + part * 8;
        float a2 = 0.f;
        #pragma unroll
        for (int i = 0; i < 8; i++) {
            float4 w4 = wp[i], m4 = mp[i];
            a2 = fmaf(w4.x, m4.x, a2); a2 = fmaf(w4.y, m4.y, a2);
            a2 = fmaf(w4.z, m4.z, a2); a2 = fmaf(w4.w, m4.w, a2);
        }
        a2 += __shfl_xor_sync(0xffffffffu, a2, 1);
        a2 += __shfl_xor_sync(0xffffffffu, a2, 2);
        a2 += __shfl_xor_sync(0xffffffffu, a2, 4);
        if (part == 0) q_s[c] = a2 + dec_b[row];
    }
    __syncthreads();

    if (t < Ln) {
        float d = 0.f;
        #pragma unroll
        for (int cc = 0; cc < HC; cc++) d = fmaf(q_s[cc], es[cc * 65 + t], d);
        p_s[t] = d * SQRT32;
    }
    __syncthreads();

    if (t < 32) {
        float v0 = p_s[t], v1 = p_s[t + 32];
        float m = fmaxf(v0, v1);
        #pragma unroll
        for (int off = 16; off; off >>= 1) m = fmaxf(m, __shfl_xor_sync(0xffffffffu, m, off));
        float e0 = __expf(v0 - m), e1 = __expf(v1 - m);
        float s = e0 + e1;
        #pragma unroll
        for (int off = 16; off; off >>= 1) s += __shfl_xor_sync(0xffffffffu, s, off);
        float pin = 1.f / s;
        p_s[t]      = e0 * pin;
        p_s[t + 32] = e1 * pin;
    }
    __syncthreads();

    if (t < HC) {
        float a3 = 0.f;
        #pragma unroll
        for (int ll = 0; ll < Ln; ll++) a3 = fmaf(p_s[ll], es[t * 65 + ll], a3);
        g_xncol[b * Cn + h * HC + t] = a3 + mask_s[h * HC + t];
    }
}

// ---------------- kernel 3: broadcast xn + (head MLP + broadcast y) ----------------
// Blocks 0..2047: 2 rows each, 16 coalesced float4 stores per thread.
// Blocks 2048..2063: per-batch fc1->fc2 in-block, then stream y.
__global__ void __launch_bounds__(256) k_bcast(float4* __restrict__ out4,
                                               const float* __restrict__ fc1_w,
                                               const float* __restrict__ fc1_g,
                                               const float* __restrict__ fc1_b,
                                               const float* __restrict__ fc2_w,
                                               const float* __restrict__ fc2_g,
                                               const float* __restrict__ fc2_b)
{
    const int t = threadIdx.x;
    if (blockIdx.x < 2048) {
        const int row = blockIdx.x * 2 + (t >> 7);      // b*Cn + c
        const int lane = t & 127;
        const float v = g_xncol[row];
        const float4 v4 = make_float4(v, v, v, v);
        float4* p = out4 + (size_t)row * 2048 + lane;
        #pragma unroll
        for (int i = 0; i < 16; i++) p[i * 128] = v4;
    } else {
        __shared__ float xn_s[Cn];
        __shared__ float y1_s[Cn];
        __shared__ float y2_s[3];
        const int b = blockIdx.x - 2048;

        xn_s[t] = g_xncol[b * Cn + t];
        __syncthreads();

        // fc1 + bn + leaky relu
        {
            float acc = 0.f;
            const float4* wr = (const float4*)(fc1_w + t * Cn);
            const float4* xr = (const float4*)xn_s;
            #pragma unroll 8
            for (int i = 0; i < 64; i++) {
                float4 w4 = wr[i], x4 = xr[i];
                acc = fmaf(w4.x, x4.x, acc); acc = fmaf(w4.y, x4.y, acc);
                acc = fmaf(w4.z, x4.z, acc); acc = fmaf(w4.w, x4.w, acc);
            }
            float y = fc1_g[t] * acc * RS_BN + fc1_b[t];
            y1_s[t] = (y >= 0.f) ? y : 0.2f * y;
        }
        __syncthreads();

        // fc2 + bn + leaky relu (3 warps -> 3 outputs)
        {
            const int w = t >> 5, lane = t & 31;
            if (w < 3) {
                const float4* wr = (const float4*)(fc2_w + w * Cn) + lane * 2;
                const float4* yr = (const float4*)y1_s + lane * 2;
                float acc = 0.f;
                #pragma unroll
                for (int i = 0; i < 2; i++) {
                    float4 w4 = wr[i], y4 = yr[i];
                    acc = fmaf(w4.x, y4.x, acc); acc = fmaf(w4.y, y4.y, acc);
                    acc = fmaf(w4.z, y4.z, acc); acc = fmaf(w4.w, y4.w, acc);
                }
                #pragma unroll
                for (int off = 16; off; off >>= 1) acc += __shfl_xor_sync(0xffffffffu, acc, off);
                if (lane == 0) {
                    float y = fc2_g[w] * acc * RS_BN + fc2_b[w];
                    y2_s[w] = (y >= 0.f) ? y : 0.2f * y;
                }
            }
        }
        __syncthreads();

        const float y0 = y2_s[0], y1 = y2_s[1], y2v = y2_s[2];
        float4 var[3];
        var[0] = make_float4(y0, y1, y2v, y0);
        var[1] = make_float4(y1, y2v, y0, y1);
        var[2] = make_float4(y2v, y0, y1, y2v);
        float4* p = out4 + (size_t)(Bn * Cn * Nn) / 4 + (size_t)b * 6144;
        for (int i = t; i < 6144; i += 256) p[i] = var[i % 3];
    }
}

// ---------------- launch ----------------
extern "C" void kernel_launch(void* const* d_in, const int* in_sizes, int n_in,
                              void* d_out, int out_size)
{
    const float* xt        = (const float*)d_in[0];
    /* xn = d_in[1] never read: fully-masked path */
    const float* weights   = (const float*)d_in[2];
    const float* mask_tok  = (const float*)d_in[3];
    const float* enc_w     = (const float*)d_in[4];
    const float* enc_b     = (const float*)d_in[5];
    const float* dec_w     = (const float*)d_in[6];
    const float* dec_b     = (const float*)d_in[7];
    const float* fc1_w     = (const float*)d_in[8];
    const float* fc1_g     = (const float*)d_in[9];
    const float* fc1_b     = (const float*)d_in[10];
    const float* fc2_w     = (const float*)d_in[11];
    const float* fc2_g     = (const float*)d_in[12];
    const float* fc2_b     = (const float*)d_in[13];
    float* out = (float*)d_out;

    k_qkv  <<<dim3(24, Bn), 256>>>(xt, enc_w, enc_b);
    k_fused<<<dim3(Hn, Bn), 256>>>(xt, weights, mask_tok, dec_w, dec_b);
    k_bcast<<<2064, 256>>>((float4*)out, fc1_w, fc1_g, fc1_b, fc2_w, fc2_g, fc2_b);
}

// round 9
// speedup vs baseline: 2.1101x; 1.0146x over previous
#include <cuda_runtime.h>
#include <math.h>

#define Bn 16
#define Cn 256
#define Ln 64
#define Nn 8192
#define Hn 8
#define HC 32          // C / H
#define Mn 12
#define SQRT32 5.656854249492381f
#define RS_BN 0.9999950000374997f   // 1/sqrt(1 + 1e-5)
#define PI_F 3.14159265358979323846f

// ---------------- scratch (device globals; no allocation) ----------------
__device__ float g_qkv[Bn * 3 * Cn * Ln];   // (B,3,C,L)
__device__ float g_xncol[Bn * Cn];          // xn_pre per (b,c) (const along n)

// packed f32x2 helpers (Blackwell): 2 fp32 FMAs per instruction, IEEE-exact
__device__ __forceinline__ void fma2(unsigned long long& d,
                                     unsigned long long a,
                                     unsigned long long b) {
    asm("fma.rn.f32x2 %0, %1, %2, %0;" : "+l"(d) : "l"(a), "l"(b));
}
__device__ __forceinline__ unsigned long long dup2(float w) {
    unsigned long long r;
    asm("mov.b64 %0, {%1, %1};" : "=l"(r) : "f"(w));
    return r;
}
__device__ __forceinline__ float2 unpk(unsigned long long a) {
    float lo, hi;
    asm("mov.b64 {%0, %1}, %2;" : "=f"(lo), "=f"(hi) : "l"(a));
    return make_float2(lo, hi);
}

// ---------------- kernel 1: qkv = enc_w @ xt + enc_b (f32x2 packed) ----------------
// grid (12, 16): 64-row tiles x batch. block 256, micro-tile 4 rows x 4 cols.
// Columns packed in pairs: X pairs come free from ld.shared.v2.b64; W needs 1 dup-mov.
__global__ void __launch_bounds__(256) k_qkv(const float* __restrict__ xt,
                                             const float* __restrict__ enc_w,
                                             const float* __restrict__ enc_b)
{
    __shared__ ulonglong2 xs4[128 * 16];     // 128 j-rows x 64 cols (16B units) = 32KB
    const int b  = blockIdx.y;
    const int rt = blockIdx.x;               // 64-row tile
    const ulonglong2* xb4 = (const ulonglong2*)(xt + b * Cn * Ln);

    const int rg = threadIdx.x >> 4;         // 0..15 -> rows rg*4..rg*4+3
    const int cg = threadIdx.x & 15;         // 0..15 -> cols cg*4..cg*4+3
    const int row0 = rt * 64 + rg * 4;

    const float4* w0p = (const float4*)(enc_w + (row0 + 0) * Cn);
    const float4* w1p = (const float4*)(enc_w + (row0 + 1) * Cn);
    const float4* w2p = (const float4*)(enc_w + (row0 + 2) * Cn);
    const float4* w3p = (const float4*)(enc_w + (row0 + 3) * Cn);

    unsigned long long acc[4][2];
    #pragma unroll
    for (int r = 0; r < 4; r++) { acc[r][0] = 0ull; acc[r][1] = 0ull; }

    for (int jc = 0; jc < 2; jc++) {
        for (int i = threadIdx.x; i < 2048; i += 256) xs4[i] = xb4[jc * 2048 + i];
        __syncthreads();
        #pragma unroll 8
        for (int j4 = 0; j4 < 32; j4++) {
            const int jg = jc * 32 + j4;
            const float4 w0 = w0p[jg], w1 = w1p[jg], w2 = w2p[jg], w3 = w3p[jg];
            #pragma unroll
            for (int jj = 0; jj < 4; jj++) {
                const ulonglong2 xv = xs4[(j4 * 4 + jj) * 16 + cg];
                const float wa = (jj == 0) ? w0.x : (jj == 1) ? w0.y : (jj == 2) ? w0.z : w0.w;
                const float wb = (jj == 0) ? w1.x : (jj == 1) ? w1.y : (jj == 2) ? w1.z : w1.w;
                const float wc = (jj == 0) ? w2.x : (jj == 1) ? w2.y : (jj == 2) ? w2.z : w2.w;
                const float wd = (jj == 0) ? w3.x : (jj == 1) ? w3.y : (jj == 2) ? w3.z : w3.w;
                const unsigned long long da = dup2(wa), db = dup2(wb);
                const unsigned long long dc = dup2(wc), dd = dup2(wd);
                fma2(acc[0][0], da, xv.x); fma2(acc[0][1], da, xv.y);
                fma2(acc[1][0], db, xv.x); fma2(acc[1][1], db, xv.y);
                fma2(acc[2][0], dc, xv.x); fma2(acc[2][1], dc, xv.y);
                fma2(acc[3][0], dd, xv.x); fma2(acc[3][1], dd, xv.y);
            }
        }
        __syncthreads();
    }

    #pragma unroll
    for (int r = 0; r < 4; r++) {
        const int o = row0 + r;
        const float bias = enc_b[o];
        const float2 p0 = unpk(acc[r][0]);
        const float2 p1 = unpk(acc[r][1]);
        float4 res = make_float4(p0.x + bias, p0.y + bias, p1.x + bias, p1.y + bias);
        ((float4*)(g_qkv + (size_t)b * 3 * Cn * Ln + o * Ln))[cg] = res;
    }
}

// ---------------- kernel 2: fused enc-attn + fourier + dec-attn ----------------
// grid (H, B), block 256. Warp w covers l = w*8 + (lane>>2), g = lane&3.
__global__ void __launch_bounds__(256) k_fused(const float* __restrict__ xt,
                                               const float* __restrict__ weights,
                                               const float* __restrict__ mask_token,
                                               const float* __restrict__ dec_w,
                                               const float* __restrict__ dec_b)
{
    __shared__ float ks[64 * 33];       // K[s][c]
    __shared__ float vs[64 * 33];       // V[s][c]
    __shared__ float sc[64 * 65];       // exp-scores per l
    __shared__ float es[HC * 65];       // encoder-out slice [c][l]
    __shared__ float ws[HC * 24];
    __shared__ float mask_s[Cn];
    __shared__ float q_s[HC];
    __shared__ float p_s[Ln];
    // total 46336 B < 48KB

    const int h = blockIdx.x, b = blockIdx.y;
    const int t = threadIdx.x;
    const int lane = t & 31;
    const int l = (t >> 5) * 8 + (lane >> 2);
    const int g = lane & 3;
    const float* qb = g_qkv + (size_t)b * 3 * Cn * Ln + (h * HC) * Ln;
    const float* kb = qb + Cn * Ln;
    const float* vb = qb + 2 * Cn * Ln;

    for (int i = t; i < 2048; i += 256) {
        int cc = i >> 6, s = i & 63;
        ks[s * 33 + cc] = kb[cc * Ln + s];
        vs[s * 33 + cc] = vb[cc * Ln + s];
    }
    mask_s[t] = mask_token[t];
    for (int i = t; i < HC * 24; i += 256) {
        int cc = i / 24, m = i - cc * 24;
        ws[i] = weights[(h * HC + cc) * 24 + m];
    }

    float q[HC];
    #pragma unroll
    for (int cc = 0; cc < HC; cc++) q[cc] = __ldg(qb + cc * Ln + l);
    __syncthreads();

    // ---- scores: this thread handles s = g, g+4, ..., g+60 ----
    float dloc[16];
    float mx = -1e30f;
    #pragma unroll
    for (int i = 0; i < 16; i++) {
        const int s = g + i * 4;
        float d = 0.f;
        #pragma unroll
        for (int cc = 0; cc < HC; cc++) d = fmaf(q[cc], ks[s * 33 + cc], d);
        d *= SQRT32;
        dloc[i] = d;
        mx = fmaxf(mx, d);
    }
    mx = fmaxf(mx, __shfl_xor_sync(0xffffffffu, mx, 1));
    mx = fmaxf(mx, __shfl_xor_sync(0xffffffffu, mx, 2));

    float sum = 0.f;
    #pragma unroll
    for (int i = 0; i < 16; i++) {
        const int s = g + i * 4;
        float e = __expf(dloc[i] - mx);
        sc[l * 65 + s] = e;
        sum += e;
    }
    sum += __shfl_xor_sync(0xffffffffu, sum, 1);
    sum += __shfl_xor_sync(0xffffffffu, sum, 2);
    const float inv = 1.f / sum;
    __syncwarp();

    // ---- weighted V (channels g*8 .. g*8+7) ----
    float acc[8];
    #pragma unroll
    for (int j = 0; j < 8; j++) acc[j] = 0.f;
    for (int s = 0; s < 64; s++) {
        const float p = sc[l * 65 + s];
        #pragma unroll
        for (int j = 0; j < 8; j++) acc[j] = fmaf(p, vs[s * 33 + g * 8 + j], acc[j]);
    }

    // ---- fourier + residual -> es ----
    const float* xrow = xt + (size_t)b * Cn * Ln + (h * HC) * Ln;
    #pragma unroll
    for (int j = 0; j < 8; j++) {
        const int cc = g * 8 + j;
        const float a = acc[j] * inv;
        const float phi = a * (PI_F / (float)Mn);
        float s1, c1;
        __sincosf(phi, &s1, &c1);
        const float* w = ws + cc * 24;
        float fv = w[Mn];
        float sm = s1, cm = c1;
        #pragma unroll
        for (int m = 1; m < Mn; m++) {
            fv = fmaf(w[m], sm, fv);
            fv = fmaf(w[Mn + m], cm, fv);
            float sn = sm * c1 + cm * s1;
            cm = cm * c1 - sm * s1;
            sm = sn;
        }
        es[cc * 65 + l] = fv + xrow[cc * Ln + l];
    }

    // ---- decoder q: 8 threads per output row ----
    {
        const int c = t >> 3, part = t & 7;
        const int row = h * HC + c;
        const float4* wp = (const float4*)(dec_w + row * Cn) + part * 8;
        const float4* mp = (const float4*)(mask_s) + part * 8;
        float a2 = 0.f;
        #pragma unroll
        for (int i = 0; i < 8; i++) {
            float4 w4 = wp[i], m4 = mp[i];
            a2 = fmaf(w4.x, m4.x, a2); a2 = fmaf(w4.y, m4.y, a2);
            a2 = fmaf(w4.z, m4.z, a2); a2 = fmaf(w4.w, m4.w, a2);
        }
        a2 += __shfl_xor_sync(0xffffffffu, a2, 1);
        a2 += __shfl_xor_sync(0xffffffffu, a2, 2);
        a2 += __shfl_xor_sync(0xffffffffu, a2, 4);
        if (part == 0) q_s[c] = a2 + dec_b[row];
    }
    __syncthreads();

    if (t < Ln) {
        float d = 0.f;
        #pragma unroll
        for (int cc = 0; cc < HC; cc++) d = fmaf(q_s[cc], es[cc * 65 + t], d);
        p_s[t] = d * SQRT32;
    }
    __syncthreads();

    if (t < 32) {
        float v0 = p_s[t], v1 = p_s[t + 32];
        float m = fmaxf(v0, v1);
        #pragma unroll
        for (int off = 16; off; off >>= 1) m = fmaxf(m, __shfl_xor_sync(0xffffffffu, m, off));
        float e0 = __expf(v0 - m), e1 = __expf(v1 - m);
        float s = e0 + e1;
        #pragma unroll
        for (int off = 16; off; off >>= 1) s += __shfl_xor_sync(0xffffffffu, s, off);
        float pin = 1.f / s;
        p_s[t]      = e0 * pin;
        p_s[t + 32] = e1 * pin;
    }
    __syncthreads();

    if (t < HC) {
        float a3 = 0.f;
        #pragma unroll
        for (int ll = 0; ll < Ln; ll++) a3 = fmaf(p_s[ll], es[t * 65 + ll], a3);
        g_xncol[b * Cn + h * HC + t] = a3 + mask_s[h * HC + t];
    }
}

// ---------------- kernel 3: broadcast xn + (head MLP + broadcast y) ----------------
__global__ void __launch_bounds__(256) k_bcast(float4* __restrict__ out4,
                                               const float* __restrict__ fc1_w,
                                               const float* __restrict__ fc1_g,
                                               const float* __restrict__ fc1_b,
                                               const float* __restrict__ fc2_w,
                                               const float* __restrict__ fc2_g,
                                               const float* __restrict__ fc2_b)
{
    const int t = threadIdx.x;
    if (blockIdx.x < 2048) {
        const int row = blockIdx.x * 2 + (t >> 7);      // b*Cn + c
        const int lane = t & 127;
        const float v = g_xncol[row];
        const float4 v4 = make_float4(v, v, v, v);
        float4* p = out4 + (size_t)row * 2048 + lane;
        #pragma unroll
        for (int i = 0; i < 16; i++) p[i * 128] = v4;
    } else {
        __shared__ float xn_s[Cn];
        __shared__ float y1_s[Cn];
        __shared__ float y2_s[3];
        const int b = blockIdx.x - 2048;

        xn_s[t] = g_xncol[b * Cn + t];
        __syncthreads();

        {
            float acc = 0.f;
            const float4* wr = (const float4*)(fc1_w + t * Cn);
            const float4* xr = (const float4*)xn_s;
            #pragma unroll 8
            for (int i = 0; i < 64; i++) {
                float4 w4 = wr[i], x4 = xr[i];
                acc = fmaf(w4.x, x4.x, acc); acc = fmaf(w4.y, x4.y, acc);
                acc = fmaf(w4.z, x4.z, acc); acc = fmaf(w4.w, x4.w, acc);
            }
            float y = fc1_g[t] * acc * RS_BN + fc1_b[t];
            y1_s[t] = (y >= 0.f) ? y : 0.2f * y;
        }
        __syncthreads();

        {
            const int w = t >> 5, lane = t & 31;
            if (w < 3) {
                const float4* wr = (const float4*)(fc2_w + w * Cn) + lane * 2;
                const float4* yr = (const float4*)y1_s + lane * 2;
                float acc = 0.f;
                #pragma unroll
                for (int i = 0; i < 2; i++) {
                    float4 w4 = wr[i], y4 = yr[i];
                    acc = fmaf(w4.x, y4.x, acc); acc = fmaf(w4.y, y4.y, acc);
                    acc = fmaf(w4.z, y4.z, acc); acc = fmaf(w4.w, y4.w, acc);
                }
                #pragma unroll
                for (int off = 16; off; off >>= 1) acc += __shfl_xor_sync(0xffffffffu, acc, off);
                if (lane == 0) {
                    float y = fc2_g[w] * acc * RS_BN + fc2_b[w];
                    y2_s[w] = (y >= 0.f) ? y : 0.2f * y;
                }
            }
        }
        __syncthreads();

        const float y0 = y2_s[0], y1 = y2_s[1], y2v = y2_s[2];
        float4 var[3];
        var[0] = make_float4(y0, y1, y2v, y0);
        var[1] = make_float4(y1, y2v, y0, y1);
        var[2] = make_float4(y2v, y0, y1, y2v);
        float4* p = out4 + (size_t)(Bn * Cn * Nn) / 4 + (size_t)b * 6144;
        for (int i = t; i < 6144; i += 256) p[i] = var[i % 3];
    }
}

// ---------------- launch ----------------
extern "C" void kernel_launch(void* const* d_in, const int* in_sizes, int n_in,
                              void* d_out, int out_size)
{
    const float* xt        = (const float*)d_in[0];
    /* xn = d_in[1] never read: fully-masked path */
    const float* weights   = (const float*)d_in[2];
    const float* mask_tok  = (const float*)d_in[3];
    const float* enc_w     = (const float*)d_in[4];
    const float* enc_b     = (const float*)d_in[5];
    const float* dec_w     = (const float*)d_in[6];
    const float* dec_b     = (const float*)d_in[7];
    const float* fc1_w     = (const float*)d_in[8];
    const float* fc1_g     = (const float*)d_in[9];
    const float* fc1_b     = (const float*)d_in[10];
    const float* fc2_w     = (const float*)d_in[11];
    const float* fc2_g     = (const float*)d_in[12];
    const float* fc2_b     = (const float*)d_in[13];
    float* out = (float*)d_out;

    k_qkv  <<<dim3(12, Bn), 256>>>(xt, enc_w, enc_b);
    k_fused<<<dim3(Hn, Bn), 256>>>(xt, weights, mask_tok, dec_w, dec_b);
    k_bcast<<<2064, 256>>>((float4*)out, fc1_w, fc1_g, fc1_b, fc2_w, fc2_g, fc2_b);
}

// round 11
// speedup vs baseline: 2.1376x; 1.0130x over previous
#include <cuda_runtime.h>
#include <math.h>

#define Bn 16
#define Cn 256
#define Ln 64
#define Nn 8192
#define Hn 8
#define HC 32          // C / H
#define Mn 12
#define KSPLIT 4
#define CnLn (Cn * Ln)
#define SQRT32 5.656854249492381f
#define RS_BN 0.9999950000374997f   // 1/sqrt(1 + 1e-5)
#define PI_F 3.14159265358979323846f

// ---------------- scratch (device globals; no allocation) ----------------
__device__ float g_qkvp[KSPLIT][Bn * 3 * Cn * Ln];  // K-split partial sums (no bias)
__device__ float g_xncol[Bn * Cn];                  // xn_pre per (b,c) (const along n)

// packed f32x2 helpers (Blackwell): 2 fp32 FMAs per instruction, IEEE-exact
__device__ __forceinline__ void fma2(unsigned long long& d,
                                     unsigned long long a,
                                     unsigned long long b) {
    asm("fma.rn.f32x2 %0, %1, %2, %0;" : "+l"(d) : "l"(a), "l"(b));
}
__device__ __forceinline__ unsigned long long dup2(float w) {
    unsigned long long r;
    asm("mov.b64 %0, {%1, %1};" : "=l"(r) : "f"(w));
    return r;
}
__device__ __forceinline__ float2 unpk(unsigned long long a) {
    float lo, hi;
    asm("mov.b64 {%0, %1}, %2;" : "=f"(lo), "=f"(hi) : "l"(a));
    return make_float2(lo, hi);
}

// ---------------- kernel 1: qkv partials (K-split x4) ----------------
// grid (12, 16, 4): 64-row tile x batch x K-quarter. block 256, 4r x 4c f32x2.
__global__ void __launch_bounds__(256) k_qkv(const float* __restrict__ xt,
                                             const float* __restrict__ enc_w)
{
    __shared__ ulonglong2 xs4[64 * 16];      // 64 j-rows x 64 cols = 16KB
    const int b  = blockIdx.y;
    const int rt = blockIdx.x;               // 64-row tile
    const int kq = blockIdx.z;               // K-quarter
    const ulonglong2* xb4 = (const ulonglong2*)(xt + b * Cn * Ln);

    for (int i = threadIdx.x; i < 1024; i += 256) xs4[i] = xb4[kq * 1024 + i];

    const int rg = threadIdx.x >> 4;         // rows rg*4..rg*4+3
    const int cg = threadIdx.x & 15;         // cols cg*4..cg*4+3
    const int row0 = rt * 64 + rg * 4;

    const float4* w0p = (const float4*)(enc_w + (row0 + 0) * Cn + kq * 64);
    const float4* w1p = (const float4*)(enc_w + (row0 + 1) * Cn + kq * 64);
    const float4* w2p = (const float4*)(enc_w + (row0 + 2) * Cn + kq * 64);
    const float4* w3p = (const float4*)(enc_w + (row0 + 3) * Cn + kq * 64);

    unsigned long long acc[4][2];
    #pragma unroll
    for (int r = 0; r < 4; r++) { acc[r][0] = 0ull; acc[r][1] = 0ull; }

    __syncthreads();
    #pragma unroll 4
    for (int j4 = 0; j4 < 16; j4++) {
        const float4 w0 = w0p[j4], w1 = w1p[j4], w2 = w2p[j4], w3 = w3p[j4];
        #pragma unroll
        for (int jj = 0; jj < 4; jj++) {
            const ulonglong2 xv = xs4[(j4 * 4 + jj) * 16 + cg];
            const float wa = (jj == 0) ? w0.x : (jj == 1) ? w0.y : (jj == 2) ? w0.z : w0.w;
            const float wb = (jj == 0) ? w1.x : (jj == 1) ? w1.y : (jj == 2) ? w1.z : w1.w;
            const float wc = (jj == 0) ? w2.x : (jj == 1) ? w2.y : (jj == 2) ? w2.z : w2.w;
            const float wd = (jj == 0) ? w3.x : (jj == 1) ? w3.y : (jj == 2) ? w3.z : w3.w;
            const unsigned long long da = dup2(wa), db = dup2(wb);
            const unsigned long long dc = dup2(wc), dd = dup2(wd);
            fma2(acc[0][0], da, xv.x); fma2(acc[0][1], da, xv.y);
            fma2(acc[1][0], db, xv.x); fma2(acc[1][1], db, xv.y);
            fma2(acc[2][0], dc, xv.x); fma2(acc[2][1], dc, xv.y);
            fma2(acc[3][0], dd, xv.x); fma2(acc[3][1], dd, xv.y);
        }
    }

    #pragma unroll
    for (int r = 0; r < 4; r++) {
        const int o = row0 + r;
        const float2 p0 = unpk(acc[r][0]);
        const float2 p1 = unpk(acc[r][1]);
        float4 res = make_float4(p0.x, p0.y, p1.x, p1.y);
        ((float4*)(g_qkvp[kq] + (size_t)b * 3 * CnLn + o * Ln))[cg] = res;
    }
}

// ---------------- kernel 2: fused enc-attn + fourier + dec-attn ----------------
// grid (H, B), block 256. Warp w covers l = w*8 + (lane>>2), g = lane&3.
// Staging sums the 4 K-split partials + bias. Score exps exchanged via shfl
// (no sc array) to make smem room for the Q stage.
__global__ void __launch_bounds__(256) k_fused(const float* __restrict__ xt,
                                               const float* __restrict__ enc_b,
                                               const float* __restrict__ weights,
                                               const float* __restrict__ mask_token,
                                               const float* __restrict__ dec_w,
                                               const float* __restrict__ dec_b)
{
    __shared__ float qs[64 * 33];       // Q[s][c]
    __shared__ float ks[64 * 33];       // K[s][c]
    __shared__ float vs[64 * 33];       // V[s][c]
    __shared__ float es[HC * 65];       // encoder-out slice [c][l]
    __shared__ float ws[HC * 24];
    __shared__ float mask_s[Cn];
    __shared__ float q_s[HC];
    __shared__ float p_s[Ln];
    // total 38144 B < 48KB

    const int h = blockIdx.x, b = blockIdx.y;
    const int t = threadIdx.x;
    const int lane = t & 31;
    const int l = (t >> 5) * 8 + (lane >> 2);
    const int g = lane & 3;

    const size_t off = (size_t)b * 3 * CnLn + (h * HC) * Ln;
    const float* a0 = g_qkvp[0] + off;
    const float* a1 = g_qkvp[1] + off;
    const float* a2 = g_qkvp[2] + off;
    const float* a3 = g_qkvp[3] + off;

    for (int i = t; i < 2048; i += 256) {
        const int cc = i >> 6, s = i & 63;
        const int idx = cc * Ln + s;
        const float bq = enc_b[h * HC + cc];
        const float bk = enc_b[Cn + h * HC + cc];
        const float bv = enc_b[2 * Cn + h * HC + cc];
        qs[s * 33 + cc] = a0[idx] + a1[idx] + a2[idx] + a3[idx] + bq;
        ks[s * 33 + cc] = a0[CnLn + idx] + a1[CnLn + idx] + a2[CnLn + idx] + a3[CnLn + idx] + bk;
        vs[s * 33 + cc] = a0[2*CnLn + idx] + a1[2*CnLn + idx] + a2[2*CnLn + idx] + a3[2*CnLn + idx] + bv;
    }
    mask_s[t] = mask_token[t];
    for (int i = t; i < HC * 24; i += 256) {
        int cc = i / 24, m = i - cc * 24;
        ws[i] = weights[(h * HC + cc) * 24 + m];
    }
    __syncthreads();

    float q[HC];
    #pragma unroll
    for (int cc = 0; cc < HC; cc++) q[cc] = qs[l * 33 + cc];

    // ---- scores: this thread handles s = g, g+4, ..., g+60 ----
    float dloc[16];
    float mx = -1e30f;
    #pragma unroll
    for (int i = 0; i < 16; i++) {
        const int s = g + i * 4;
        float d = 0.f;
        #pragma unroll
        for (int cc = 0; cc < HC; cc++) d = fmaf(q[cc], ks[s * 33 + cc], d);
        d *= SQRT32;
        dloc[i] = d;
        mx = fmaxf(mx, d);
    }
    mx = fmaxf(mx, __shfl_xor_sync(0xffffffffu, mx, 1));
    mx = fmaxf(mx, __shfl_xor_sync(0xffffffffu, mx, 2));

    float sum = 0.f;
    #pragma unroll
    for (int i = 0; i < 16; i++) {
        const float e = __expf(dloc[i] - mx);
        dloc[i] = e;
        sum += e;
    }
    sum += __shfl_xor_sync(0xffffffffu, sum, 1);
    sum += __shfl_xor_sync(0xffffffffu, sum, 2);
    const float inv = 1.f / sum;

    // ---- weighted V (channels g*8..g*8+7); exps exchanged via shfl ----
    float acc[8];
    #pragma unroll
    for (int j = 0; j < 8; j++) acc[j] = 0.f;
    #pragma unroll 16
    for (int s = 0; s < 64; s++) {
        const int src = (lane & 28) | (s & 3);
        const float p = __shfl_sync(0xffffffffu, dloc[s >> 2], src);
        #pragma unroll
        for (int j = 0; j < 8; j++) acc[j] = fmaf(p, vs[s * 33 + g * 8 + j], acc[j]);
    }

    // ---- fourier + residual -> es ----
    const float* xrow = xt + (size_t)b * Cn * Ln + (h * HC) * Ln;
    #pragma unroll
    for (int j = 0; j < 8; j++) {
        const int cc = g * 8 + j;
        const float a = acc[j] * inv;
        const float phi = a * (PI_F / (float)Mn);
        float s1, c1;
        __sincosf(phi, &s1, &c1);
        const float* w = ws + cc * 24;
        float fv = w[Mn];
        float sm = s1, cm = c1;
        #pragma unroll
        for (int m = 1; m < Mn; m++) {
            fv = fmaf(w[m], sm, fv);
            fv = fmaf(w[Mn + m], cm, fv);
            float sn = sm * c1 + cm * s1;
            cm = cm * c1 - sm * s1;
            sm = sn;
        }
        es[cc * 65 + l] = fv + xrow[cc * Ln + l];
    }

    // ---- decoder q: 8 threads per output row ----
    {
        const int c = t >> 3, part = t & 7;
        const int row = h * HC + c;
        const float4* wp = (const float4*)(dec_w + row * Cn) + part * 8;
        const float4* mp = (const float4*)(mask_s) + part * 8;
        float a4 = 0.f;
        #pragma unroll
        for (int i = 0; i < 8; i++) {
            float4 w4 = wp[i], m4 = mp[i];
            a4 = fmaf(w4.x, m4.x, a4); a4 = fmaf(w4.y, m4.y, a4);
            a4 = fmaf(w4.z, m4.z, a4); a4 = fmaf(w4.w, m4.w, a4);
        }
        a4 += __shfl_xor_sync(0xffffffffu, a4, 1);
        a4 += __shfl_xor_sync(0xffffffffu, a4, 2);
        a4 += __shfl_xor_sync(0xffffffffu, a4, 4);
        if (part == 0) q_s[c] = a4 + dec_b[row];
    }
    __syncthreads();

    if (t < Ln) {
        float d = 0.f;
        #pragma unroll
        for (int cc = 0; cc < HC; cc++) d = fmaf(q_s[cc], es[cc * 65 + t], d);
        p_s[t] = d * SQRT32;
    }
    __syncthreads();

    if (t < 32) {
        float v0 = p_s[t], v1 = p_s[t + 32];
        float m = fmaxf(v0, v1);
        #pragma unroll
        for (int off2 = 16; off2; off2 >>= 1) m = fmaxf(m, __shfl_xor_sync(0xffffffffu, m, off2));
        float e0 = __expf(v0 - m), e1 = __expf(v1 - m);
        float s = e0 + e1;
        #pragma unroll
        for (int off2 = 16; off2; off2 >>= 1) s += __shfl_xor_sync(0xffffffffu, s, off2);
        float pin = 1.f / s;
        p_s[t]      = e0 * pin;
        p_s[t + 32] = e1 * pin;
    }
    __syncthreads();

    if (t < HC) {
        float a5 = 0.f;
        #pragma unroll
        for (int ll = 0; ll < Ln; ll++) a5 = fmaf(p_s[ll], es[t * 65 + ll], a5);
        g_xncol[b * Cn + h * HC + t] = a5 + mask_s[h * HC + t];
    }
}

// ---------------- kernel 3: broadcast xn + (head MLP + broadcast y) ----------------
__global__ void __launch_bounds__(256) k_bcast(float4* __restrict__ out4,
                                               const float* __restrict__ fc1_w,
                                               const float* __restrict__ fc1_g,
                                               const float* __restrict__ fc1_b,
                                               const float* __restrict__ fc2_w,
                                               const float* __restrict__ fc2_g,
                                               const float* __restrict__ fc2_b)
{
    const int t = threadIdx.x;
    if (blockIdx.x < 2048) {
        const int row = blockIdx.x * 2 + (t >> 7);      // b*Cn + c
        const int lane = t & 127;
        const float v = g_xncol[row];
        const float4 v4 = make_float4(v, v, v, v);
        float4* p = out4 + (size_t)row * 2048 + lane;
        #pragma unroll
        for (int i = 0; i < 16; i++) p[i * 128] = v4;
    } else {
        __shared__ float xn_s[Cn];
        __shared__ float y1_s[Cn];
        __shared__ float y2_s[3];
        const int b = blockIdx.x - 2048;

        xn_s[t] = g_xncol[b * Cn + t];
        __syncthreads();

        {
            float acc = 0.f;
            const float4* wr = (const float4*)(fc1_w + t * Cn);
            const float4* xr = (const float4*)xn_s;
            #pragma unroll 8
            for (int i = 0; i < 64; i++) {
                float4 w4 = wr[i], x4 = xr[i];
                acc = fmaf(w4.x, x4.x, acc); acc = fmaf(w4.y, x4.y, acc);
                acc = fmaf(w4.z, x4.z, acc); acc = fmaf(w4.w, x4.w, acc);
            }
            float y = fc1_g[t] * acc * RS_BN + fc1_b[t];
            y1_s[t] = (y >= 0.f) ? y : 0.2f * y;
        }
        __syncthreads();

        {
            const int w = t >> 5, lane = t & 31;
            if (w < 3) {
                const float4* wr = (const float4*)(fc2_w + w * Cn) + lane * 2;
                const float4* yr = (const float4*)y1_s + lane * 2;
                float acc = 0.f;
                #pragma unroll
                for (int i = 0; i < 2; i++) {
                    float4 w4 = wr[i], y4 = yr[i];
                    acc = fmaf(w4.x, y4.x, acc); acc = fmaf(w4.y, y4.y, acc);
                    acc = fmaf(w4.z, y4.z, acc); acc = fmaf(w4.w, y4.w, acc);
                }
                #pragma unroll
                for (int off = 16; off; off >>= 1) acc += __shfl_xor_sync(0xffffffffu, acc, off);
                if (lane == 0) {
                    float y = fc2_g[w] * acc * RS_BN + fc2_b[w];
                    y2_s[w] = (y >= 0.f) ? y : 0.2f * y;
                }
            }
        }
        __syncthreads();

        const float y0 = y2_s[0], y1 = y2_s[1], y2v = y2_s[2];
        float4 var[3];
        var[0] = make_float4(y0, y1, y2v, y0);
        var[1] = make_float4(y1, y2v, y0, y1);
        var[2] = make_float4(y2v, y0, y1, y2v);
        float4* p = out4 + (size_t)(Bn * Cn * Nn) / 4 + (size_t)b * 6144;
        for (int i = t; i < 6144; i += 256) p[i] = var[i % 3];
    }
}

// ---------------- launch ----------------
extern "C" void kernel_launch(void* const* d_in, const int* in_sizes, int n_in,
                              void* d_out, int out_size)
{
    const float* xt        = (const float*)d_in[0];
    /* xn = d_in[1] never read: fully-masked path */
    const float* weights   = (const float*)d_in[2];
    const float* mask_tok  = (const float*)d_in[3];
    const float* enc_w     = (const float*)d_in[4];
    const float* enc_b     = (const float*)d_in[5];
    const float* dec_w     = (const float*)d_in[6];
    const float* dec_b     = (const float*)d_in[7];
    const float* fc1_w     = (const float*)d_in[8];
    const float* fc1_g     = (const float*)d_in[9];
    const float* fc1_b     = (const float*)d_in[10];
    const float* fc2_w     = (const float*)d_in[11];
    const float* fc2_g     = (const float*)d_in[12];
    const float* fc2_b     = (const float*)d_in[13];
    float* out = (float*)d_out;

    k_qkv  <<<dim3(12, Bn, KSPLIT), 256>>>(xt, enc_w);
    k_fused<<<dim3(Hn, Bn), 256>>>(xt, enc_b, weights, mask_tok, dec_w, dec_b);
    k_bcast<<<2064, 256>>>((float4*)out, fc1_w, fc1_g, fc1_b, fc2_w, fc2_g, fc2_b);
}